// round 1
// baseline (speedup 1.0000x reference)
#include <cuda_runtime.h>
#include <cuda_bf16.h>
#include <mma.h>
#include <math.h>

using namespace nvcuda;

// Problem sizes (fixed)
#define B   64
#define S   2048
#define M   1024   // memory feature dim (K of scores GEMM)
#define D   1024   // decoder feature dim (N of scores GEMM)

// Scores GEMM tiling
#define BM 128
#define BN 128
#define BK 32
#define LDA 36     // sA row stride (floats), 144B (16B-aligned rows)
#define LDB 132    // sB row stride
#define LDC 132

// Scratch (no allocations allowed)
__device__ float g_scores[B * S];      // 512 KB
__device__ float g_decf[B * D];        // 256 KB

// ---------------------------------------------------------------------------
// Kernel 0: zero the scores accumulator (d-tiles atomically add into it)
// ---------------------------------------------------------------------------
__global__ __launch_bounds__(512) void zero_scores_kernel() {
    int i = blockIdx.x * 512 + threadIdx.x;
    g_scores[i] = 0.0f;
}

// ---------------------------------------------------------------------------
// Kernel 1: dec_feat[b][d] = sum_m decoder_state[b][m] * W_dec[m][d]
// grid (4 d-chunks, 16 b-groups), block 256. Each block: 4 batches x 256 d.
// ---------------------------------------------------------------------------
__global__ __launch_bounds__(256) void dec_feat_kernel(
    const float* __restrict__ decoder_state,
    const float* __restrict__ W_dec)
{
    __shared__ float ds[4][M];
    int tid = threadIdx.x;
    int d   = blockIdx.x * 256 + tid;
    int bg  = blockIdx.y * 4;

    for (int i = tid; i < 4 * M; i += 256) {
        ds[i >> 10][i & (M - 1)] = decoder_state[(bg + (i >> 10)) * M + (i & (M - 1))];
    }
    __syncthreads();

    float acc0 = 0.f, acc1 = 0.f, acc2 = 0.f, acc3 = 0.f;
    for (int m = 0; m < M; m++) {
        float w = W_dec[(size_t)m * D + d];
        acc0 += ds[0][m] * w;
        acc1 += ds[1][m] * w;
        acc2 += ds[2][m] * w;
        acc3 += ds[3][m] * w;
    }
    g_decf[(bg + 0) * D + d] = acc0;
    g_decf[(bg + 1) * D + d] = acc1;
    g_decf[(bg + 2) * D + d] = acc2;
    g_decf[(bg + 3) * D + d] = acc3;
}

// ---------------------------------------------------------------------------
// Kernel 2: fused scores GEMM (tf32 wmma) + tanh + Wv-dot epilogue.
// C[s][d] = sum_m mem[b][s][m] * W_mem[m][d]   (A row-major, B row-major)
// partial_score[s] = sum_{d in tile} Wv[d] * tanh(C[s][d] + dec_feat[b][d])
// atomicAdd into g_scores.
// grid (16 s-tiles, 8 d-tiles, 64 b), block 256 (8 warps, 4x2 layout).
// ---------------------------------------------------------------------------
extern __shared__ float smem_dyn[];

__global__ __launch_bounds__(256) void scores_kernel(
    const float* __restrict__ memory_bank,
    const float* __restrict__ W_mem,
    const float* __restrict__ W_v)
{
    int tid = threadIdx.x;
    int wid = tid >> 5;
    int wr  = wid >> 1;   // 0..3  -> warp row (32 rows each)
    int wc  = wid & 1;    // 0..1  -> warp col (64 cols each)

    int s_base = blockIdx.x * BM;
    int d_base = blockIdx.y * BN;
    int b      = blockIdx.z;

    float* sA = smem_dyn;                 // [BM][LDA]  = 128*36 floats (18432 B)
    float* sB = smem_dyn + BM * LDA;      // [BK][LDB]  = 32*132  floats (16896 B)
    float* sC = smem_dyn;                 // reused after K loop: [BM][LDC] (67584 B)

    wmma::fragment<wmma::accumulator, 16, 16, 8, float> c_frag[2][4];
    #pragma unroll
    for (int i = 0; i < 2; i++)
        #pragma unroll
        for (int j = 0; j < 4; j++)
            wmma::fill_fragment(c_frag[i][j], 0.0f);

    const float* Abase = memory_bank + ((size_t)b * S + s_base) * M;

    for (int k0 = 0; k0 < M; k0 += BK) {
        // Load A tile: BM x BK  (128x32) as float4
        #pragma unroll
        for (int it = 0; it < 4; it++) {
            int i   = tid + it * 256;             // 0..1023
            int row = i >> 3;                     // /8
            int c4  = i & 7;
            float4 v = *reinterpret_cast<const float4*>(
                Abase + (size_t)row * M + k0 + c4 * 4);
            *reinterpret_cast<float4*>(&sA[row * LDA + c4 * 4]) = v;
        }
        // Load B tile: BK x BN (32x128) as float4 (W_mem row-major: [m][d])
        #pragma unroll
        for (int it = 0; it < 4; it++) {
            int i   = tid + it * 256;
            int row = i >> 5;                     // /32 -> k row
            int c4  = i & 31;
            float4 v = *reinterpret_cast<const float4*>(
                W_mem + (size_t)(k0 + row) * D + d_base + c4 * 4);
            *reinterpret_cast<float4*>(&sB[row * LDB + c4 * 4]) = v;
        }
        __syncthreads();

        #pragma unroll
        for (int kk = 0; kk < BK; kk += 8) {
            wmma::fragment<wmma::matrix_a, 16, 16, 8, wmma::precision::tf32, wmma::row_major> a_frag[2];
            wmma::fragment<wmma::matrix_b, 16, 16, 8, wmma::precision::tf32, wmma::row_major> b_frag[4];
            #pragma unroll
            for (int i = 0; i < 2; i++) {
                wmma::load_matrix_sync(a_frag[i], &sA[(wr * 32 + i * 16) * LDA + kk], LDA);
                #pragma unroll
                for (int e = 0; e < a_frag[i].num_elements; e++)
                    a_frag[i].x[e] = wmma::__float_to_tf32(a_frag[i].x[e]);
            }
            #pragma unroll
            for (int j = 0; j < 4; j++) {
                wmma::load_matrix_sync(b_frag[j], &sB[kk * LDB + wc * 64 + j * 16], LDB);
                #pragma unroll
                for (int e = 0; e < b_frag[j].num_elements; e++)
                    b_frag[j].x[e] = wmma::__float_to_tf32(b_frag[j].x[e]);
            }
            #pragma unroll
            for (int i = 0; i < 2; i++)
                #pragma unroll
                for (int j = 0; j < 4; j++)
                    wmma::mma_sync(c_frag[i][j], a_frag[i], b_frag[j], c_frag[i][j]);
        }
        __syncthreads();
    }

    // Dump accumulators to shared (reusing the A/B buffers)
    #pragma unroll
    for (int i = 0; i < 2; i++)
        #pragma unroll
        for (int j = 0; j < 4; j++)
            wmma::store_matrix_sync(&sC[(wr * 32 + i * 16) * LDC + wc * 64 + j * 16],
                                    c_frag[i][j], LDC, wmma::mem_row_major);
    __syncthreads();

    // Epilogue: thread t handles row r = t/2, column half h = t&1 (64 cols)
    int r = tid >> 1;
    int h = tid & 1;
    const float* decf = g_decf + b * D + d_base;
    const float* wv   = W_v + d_base;
    float partial = 0.0f;
    #pragma unroll 4
    for (int c = 0; c < 64; c++) {
        int col = h * 64 + c;
        float x = sC[r * LDC + col] + decf[col];
        partial += wv[col] * tanhf(x);
    }
    partial += __shfl_xor_sync(0xFFFFFFFFu, partial, 1);
    if (h == 0)
        atomicAdd(&g_scores[b * S + s_base + r], partial);
}

// ---------------------------------------------------------------------------
// Kernel 3: masked softmax over S per batch. grid 64, block 256 (8 elems/thr)
// Writes attn into d_out attn region.
// ---------------------------------------------------------------------------
__global__ __launch_bounds__(256) void softmax_kernel(
    const int* __restrict__ src_mask,
    float* __restrict__ attn_out)
{
    __shared__ float red[8];
    int b = blockIdx.x, tid = threadIdx.x;
    int lane = tid & 31, wid = tid >> 5;

    float v[8];
    float mx = -3.4e38f;
    #pragma unroll
    for (int j = 0; j < 8; j++) {
        int idx = tid + j * 256;
        float s = g_scores[b * S + idx];
        if (src_mask[b * S + idx] == 0) s = -3.4e38f;
        v[j] = s;
        mx = fmaxf(mx, s);
    }
    #pragma unroll
    for (int off = 16; off > 0; off >>= 1)
        mx = fmaxf(mx, __shfl_xor_sync(0xFFFFFFFFu, mx, off));
    if (lane == 0) red[wid] = mx;
    __syncthreads();
    if (tid == 0) {
        float m2 = red[0];
        #pragma unroll
        for (int w = 1; w < 8; w++) m2 = fmaxf(m2, red[w]);
        red[0] = m2;
    }
    __syncthreads();
    mx = red[0];
    __syncthreads();

    float e[8];
    float sum = 0.0f;
    #pragma unroll
    for (int j = 0; j < 8; j++) {
        e[j] = __expf(v[j] - mx);
        sum += e[j];
    }
    #pragma unroll
    for (int off = 16; off > 0; off >>= 1)
        sum += __shfl_xor_sync(0xFFFFFFFFu, sum, off);
    if (lane == 0) red[wid] = sum;
    __syncthreads();
    if (tid == 0) {
        float s2 = 0.0f;
        #pragma unroll
        for (int w = 0; w < 8; w++) s2 += red[w];
        red[0] = s2;
    }
    __syncthreads();
    float inv = 1.0f / red[0];

    #pragma unroll
    for (int j = 0; j < 8; j++)
        attn_out[b * S + tid + j * 256] = e[j] * inv;
}

// ---------------------------------------------------------------------------
// Kernel 4: context[b][m] = sum_s attn[b][s] * mem[b][s][m]
// grid (4 m-chunks, 64 b), block 256. Streams 512 MB once at HBM BW.
// ---------------------------------------------------------------------------
__global__ __launch_bounds__(256) void context_kernel(
    const float* __restrict__ attn,
    const float* __restrict__ memory_bank,
    float* __restrict__ ctx_out)
{
    __shared__ float sa[S];
    int tid = threadIdx.x;
    int b   = blockIdx.y;
    int m0  = blockIdx.x * 256;

    #pragma unroll
    for (int j = 0; j < 8; j++)
        sa[tid + j * 256] = attn[b * S + tid + j * 256];
    __syncthreads();

    const float* base = memory_bank + (size_t)b * S * M + m0 + tid;
    float acc0 = 0.f, acc1 = 0.f, acc2 = 0.f, acc3 = 0.f;
    for (int s = 0; s < S; s += 4) {
        acc0 += sa[s + 0] * base[(size_t)(s + 0) * M];
        acc1 += sa[s + 1] * base[(size_t)(s + 1) * M];
        acc2 += sa[s + 2] * base[(size_t)(s + 2) * M];
        acc3 += sa[s + 3] * base[(size_t)(s + 3) * M];
    }
    ctx_out[b * M + m0 + tid] = (acc0 + acc1) + (acc2 + acc3);
}

// ---------------------------------------------------------------------------
// Launch
// ---------------------------------------------------------------------------
extern "C" void kernel_launch(void* const* d_in, const int* in_sizes, int n_in,
                              void* d_out, int out_size)
{
    const float* decoder_state = (const float*)d_in[0];
    const float* memory_bank   = (const float*)d_in[1];
    const int*   src_mask      = (const int*)  d_in[2];
    const float* W_v           = (const float*)d_in[3];
    const float* W_dec         = (const float*)d_in[4];
    const float* W_mem         = (const float*)d_in[5];

    float* out  = (float*)d_out;
    float* ctx  = out;                 // [64, 1024]
    float* attn = out + B * M;         // [64, 2048]

    // Scores kernel needs 67584 B of dynamic smem (C-tile dump)
    static bool attr_set = false;
    (void)attr_set;
    cudaFuncSetAttribute(scores_kernel,
                         cudaFuncAttributeMaxDynamicSharedMemorySize, 69632);

    zero_scores_kernel<<<B * S / 512, 512>>>();
    dec_feat_kernel<<<dim3(D / 256, B / 4), 256>>>(decoder_state, W_dec);
    scores_kernel<<<dim3(S / BM, D / BN, B), 256, 69632>>>(memory_bank, W_mem, W_v);
    softmax_kernel<<<B, 256>>>(src_mask, attn);
    context_kernel<<<dim3(M / 256, B), 256>>>(attn, memory_bank, ctx);
}

// round 2
// speedup vs baseline: 1.0027x; 1.0027x over previous
#include <cuda_runtime.h>
#include <cuda_bf16.h>
#include <mma.h>
#include <math.h>

using namespace nvcuda;

// Problem sizes (fixed)
#define B   64
#define S   2048
#define M   1024   // memory feature dim (K of scores GEMM)
#define D   1024   // decoder feature dim (N of scores GEMM)

// Scores GEMM tiling
#define BM 128
#define BN 128
#define BK 32
#define LDA 36     // sA row stride (floats), 144B (16B-aligned rows)
#define LDB 132    // sB row stride
#define LDC 132

// Scratch (no allocations allowed)
__device__ float g_scores[B * S];      // 512 KB
__device__ float g_decf[B * D];        // 256 KB

// ---------------------------------------------------------------------------
// Kernel 0: zero the scores accumulator (d-tiles atomically add into it)
// ---------------------------------------------------------------------------
__global__ __launch_bounds__(512) void zero_scores_kernel() {
    int i = blockIdx.x * 512 + threadIdx.x;
    g_scores[i] = 0.0f;
}

// ---------------------------------------------------------------------------
// Kernel 1: dec_feat[b][d] = sum_m decoder_state[b][m] * W_dec[m][d]
// grid (4 d-chunks, 16 b-groups), block 256. Each block: 4 batches x 256 d.
// ---------------------------------------------------------------------------
__global__ __launch_bounds__(256) void dec_feat_kernel(
    const float* __restrict__ decoder_state,
    const float* __restrict__ W_dec)
{
    __shared__ float ds[4][M];
    int tid = threadIdx.x;
    int d   = blockIdx.x * 256 + tid;
    int bg  = blockIdx.y * 4;

    for (int i = tid; i < 4 * M; i += 256) {
        ds[i >> 10][i & (M - 1)] = decoder_state[(bg + (i >> 10)) * M + (i & (M - 1))];
    }
    __syncthreads();

    float acc0 = 0.f, acc1 = 0.f, acc2 = 0.f, acc3 = 0.f;
    for (int m = 0; m < M; m++) {
        float w = W_dec[(size_t)m * D + d];
        acc0 += ds[0][m] * w;
        acc1 += ds[1][m] * w;
        acc2 += ds[2][m] * w;
        acc3 += ds[3][m] * w;
    }
    g_decf[(bg + 0) * D + d] = acc0;
    g_decf[(bg + 1) * D + d] = acc1;
    g_decf[(bg + 2) * D + d] = acc2;
    g_decf[(bg + 3) * D + d] = acc3;
}

// ---------------------------------------------------------------------------
// Kernel 2: fused scores GEMM (tf32 wmma) + tanh + Wv-dot epilogue.
// C[s][d] = sum_m mem[b][s][m] * W_mem[m][d]   (A row-major, B row-major)
// partial_score[s] = sum_{d in tile} Wv[d] * tanh(C[s][d] + dec_feat[b][d])
// atomicAdd into g_scores.
// grid (16 s-tiles, 8 d-tiles, 64 b), block 256 (8 warps, 4x2 layout).
// ---------------------------------------------------------------------------
extern __shared__ float smem_dyn[];

__global__ __launch_bounds__(256) void scores_kernel(
    const float* __restrict__ memory_bank,
    const float* __restrict__ W_mem,
    const float* __restrict__ W_v)
{
    int tid = threadIdx.x;
    int wid = tid >> 5;
    int wr  = wid >> 1;   // 0..3  -> warp row (32 rows each)
    int wc  = wid & 1;    // 0..1  -> warp col (64 cols each)

    int s_base = blockIdx.x * BM;
    int d_base = blockIdx.y * BN;
    int b      = blockIdx.z;

    float* sA = smem_dyn;                 // [BM][LDA]  = 128*36 floats (18432 B)
    float* sB = smem_dyn + BM * LDA;      // [BK][LDB]  = 32*132  floats (16896 B)
    float* sC = smem_dyn;                 // reused after K loop: [BM][LDC] (67584 B)

    wmma::fragment<wmma::accumulator, 16, 16, 8, float> c_frag[2][4];
    #pragma unroll
    for (int i = 0; i < 2; i++)
        #pragma unroll
        for (int j = 0; j < 4; j++)
            wmma::fill_fragment(c_frag[i][j], 0.0f);

    const float* Abase = memory_bank + ((size_t)b * S + s_base) * M;

    for (int k0 = 0; k0 < M; k0 += BK) {
        // Load A tile: BM x BK  (128x32) as float4
        #pragma unroll
        for (int it = 0; it < 4; it++) {
            int i   = tid + it * 256;             // 0..1023
            int row = i >> 3;                     // /8
            int c4  = i & 7;
            float4 v = *reinterpret_cast<const float4*>(
                Abase + (size_t)row * M + k0 + c4 * 4);
            *reinterpret_cast<float4*>(&sA[row * LDA + c4 * 4]) = v;
        }
        // Load B tile: BK x BN (32x128) as float4 (W_mem row-major: [m][d])
        #pragma unroll
        for (int it = 0; it < 4; it++) {
            int i   = tid + it * 256;
            int row = i >> 5;                     // /32 -> k row
            int c4  = i & 31;
            float4 v = *reinterpret_cast<const float4*>(
                W_mem + (size_t)(k0 + row) * D + d_base + c4 * 4);
            *reinterpret_cast<float4*>(&sB[row * LDB + c4 * 4]) = v;
        }
        __syncthreads();

        #pragma unroll
        for (int kk = 0; kk < BK; kk += 8) {
            wmma::fragment<wmma::matrix_a, 16, 16, 8, wmma::precision::tf32, wmma::row_major> a_frag[2];
            wmma::fragment<wmma::matrix_b, 16, 16, 8, wmma::precision::tf32, wmma::row_major> b_frag[4];
            #pragma unroll
            for (int i = 0; i < 2; i++) {
                wmma::load_matrix_sync(a_frag[i], &sA[(wr * 32 + i * 16) * LDA + kk], LDA);
                #pragma unroll
                for (int e = 0; e < a_frag[i].num_elements; e++)
                    a_frag[i].x[e] = wmma::__float_to_tf32(a_frag[i].x[e]);
            }
            #pragma unroll
            for (int j = 0; j < 4; j++) {
                wmma::load_matrix_sync(b_frag[j], &sB[kk * LDB + wc * 64 + j * 16], LDB);
                #pragma unroll
                for (int e = 0; e < b_frag[j].num_elements; e++)
                    b_frag[j].x[e] = wmma::__float_to_tf32(b_frag[j].x[e]);
            }
            #pragma unroll
            for (int i = 0; i < 2; i++)
                #pragma unroll
                for (int j = 0; j < 4; j++)
                    wmma::mma_sync(c_frag[i][j], a_frag[i], b_frag[j], c_frag[i][j]);
        }
        __syncthreads();
    }

    // Dump accumulators to shared (reusing the A/B buffers)
    #pragma unroll
    for (int i = 0; i < 2; i++)
        #pragma unroll
        for (int j = 0; j < 4; j++)
            wmma::store_matrix_sync(&sC[(wr * 32 + i * 16) * LDC + wc * 64 + j * 16],
                                    c_frag[i][j], LDC, wmma::mem_row_major);
    __syncthreads();

    // Epilogue: thread t handles row r = t/2, column half h = t&1 (64 cols)
    int r = tid >> 1;
    int h = tid & 1;
    const float* decf = g_decf + b * D + d_base;
    const float* wv   = W_v + d_base;
    float partial = 0.0f;
    #pragma unroll 4
    for (int c = 0; c < 64; c++) {
        int col = h * 64 + c;
        float x = sC[r * LDC + col] + decf[col];
        partial += wv[col] * tanhf(x);
    }
    partial += __shfl_xor_sync(0xFFFFFFFFu, partial, 1);
    if (h == 0)
        atomicAdd(&g_scores[b * S + s_base + r], partial);
}

// ---------------------------------------------------------------------------
// Kernel 3: masked softmax over S per batch. grid 64, block 256 (8 elems/thr)
// Writes attn into d_out attn region.
// ---------------------------------------------------------------------------
__global__ __launch_bounds__(256) void softmax_kernel(
    const int* __restrict__ src_mask,
    float* __restrict__ attn_out)
{
    __shared__ float red[8];
    int b = blockIdx.x, tid = threadIdx.x;
    int lane = tid & 31, wid = tid >> 5;

    float v[8];
    float mx = -3.4e38f;
    #pragma unroll
    for (int j = 0; j < 8; j++) {
        int idx = tid + j * 256;
        float s = g_scores[b * S + idx];
        if (src_mask[b * S + idx] == 0) s = -3.4e38f;
        v[j] = s;
        mx = fmaxf(mx, s);
    }
    #pragma unroll
    for (int off = 16; off > 0; off >>= 1)
        mx = fmaxf(mx, __shfl_xor_sync(0xFFFFFFFFu, mx, off));
    if (lane == 0) red[wid] = mx;
    __syncthreads();
    if (tid == 0) {
        float m2 = red[0];
        #pragma unroll
        for (int w = 1; w < 8; w++) m2 = fmaxf(m2, red[w]);
        red[0] = m2;
    }
    __syncthreads();
    mx = red[0];
    __syncthreads();

    float e[8];
    float sum = 0.0f;
    #pragma unroll
    for (int j = 0; j < 8; j++) {
        e[j] = __expf(v[j] - mx);
        sum += e[j];
    }
    #pragma unroll
    for (int off = 16; off > 0; off >>= 1)
        sum += __shfl_xor_sync(0xFFFFFFFFu, sum, off);
    if (lane == 0) red[wid] = sum;
    __syncthreads();
    if (tid == 0) {
        float s2 = 0.0f;
        #pragma unroll
        for (int w = 0; w < 8; w++) s2 += red[w];
        red[0] = s2;
    }
    __syncthreads();
    float inv = 1.0f / red[0];

    #pragma unroll
    for (int j = 0; j < 8; j++)
        attn_out[b * S + tid + j * 256] = e[j] * inv;
}

// ---------------------------------------------------------------------------
// Kernel 4: context[b][m] = sum_s attn[b][s] * mem[b][s][m]
// grid (4 m-chunks, 64 b), block 256. Streams 512 MB once at HBM BW.
// ---------------------------------------------------------------------------
__global__ __launch_bounds__(256) void context_kernel(
    const float* __restrict__ attn,
    const float* __restrict__ memory_bank,
    float* __restrict__ ctx_out)
{
    __shared__ float sa[S];
    int tid = threadIdx.x;
    int b   = blockIdx.y;
    int m0  = blockIdx.x * 256;

    #pragma unroll
    for (int j = 0; j < 8; j++)
        sa[tid + j * 256] = attn[b * S + tid + j * 256];
    __syncthreads();

    const float* base = memory_bank + (size_t)b * S * M + m0 + tid;
    float acc0 = 0.f, acc1 = 0.f, acc2 = 0.f, acc3 = 0.f;
    for (int s = 0; s < S; s += 4) {
        acc0 += sa[s + 0] * base[(size_t)(s + 0) * M];
        acc1 += sa[s + 1] * base[(size_t)(s + 1) * M];
        acc2 += sa[s + 2] * base[(size_t)(s + 2) * M];
        acc3 += sa[s + 3] * base[(size_t)(s + 3) * M];
    }
    ctx_out[b * M + m0 + tid] = (acc0 + acc1) + (acc2 + acc3);
}

// ---------------------------------------------------------------------------
// Launch
// ---------------------------------------------------------------------------
extern "C" void kernel_launch(void* const* d_in, const int* in_sizes, int n_in,
                              void* d_out, int out_size)
{
    const float* decoder_state = (const float*)d_in[0];
    const float* memory_bank   = (const float*)d_in[1];
    const int*   src_mask      = (const int*)  d_in[2];
    const float* W_v           = (const float*)d_in[3];
    const float* W_dec         = (const float*)d_in[4];
    const float* W_mem         = (const float*)d_in[5];

    float* out  = (float*)d_out;
    float* ctx  = out;                 // [64, 1024]
    float* attn = out + B * M;         // [64, 2048]

    // Scores kernel needs 67584 B of dynamic smem (C-tile dump)
    static bool attr_set = false;
    (void)attr_set;
    cudaFuncSetAttribute(scores_kernel,
                         cudaFuncAttributeMaxDynamicSharedMemorySize, 69632);

    zero_scores_kernel<<<B * S / 512, 512>>>();
    dec_feat_kernel<<<dim3(D / 256, B / 4), 256>>>(decoder_state, W_dec);
    scores_kernel<<<dim3(S / BM, D / BN, B), 256, 69632>>>(memory_bank, W_mem, W_v);
    softmax_kernel<<<B, 256>>>(src_mask, attn);
    context_kernel<<<dim3(M / 256, B), 256>>>(attn, memory_bank, ctx);
}

// round 4
// speedup vs baseline: 2.6247x; 2.6175x over previous
#include <cuda_runtime.h>
#include <cuda_bf16.h>
#include <cstdint>
#include <math.h>

// Problem sizes (fixed)
#define B_   64
#define S_   2048
#define M_   1024   // K of scores GEMM (memory feature dim)
#define D_   1024   // N of scores GEMM (decoder feature dim)

// ---------------------------------------------------------------------------
// Scratch (no allocations allowed)
// ---------------------------------------------------------------------------
__device__ float g_scores[B_ * S_];          // 512 KB
__device__ float g_decf[B_ * D_];            // 256 KB
__device__ float g_Wt[D_ * M_];              // 4 MB: W_mem transposed [d][k]

// ---------------------------------------------------------------------------
// Helpers
// ---------------------------------------------------------------------------
__device__ __forceinline__ uint32_t smem_u32(const void* p) {
    uint32_t a;
    asm("{ .reg .u64 t; cvta.to.shared.u64 t, %1; cvt.u32.u64 %0, t; }"
        : "=r"(a) : "l"(p));
    return a;
}

__device__ __forceinline__ void cp_async16(uint32_t dst, const void* src) {
    asm volatile("cp.async.cg.shared.global [%0], [%1], 16;"
                 :: "r"(dst), "l"(src));
}
#define CP_ASYNC_COMMIT() asm volatile("cp.async.commit_group;" ::: "memory")
#define CP_ASYNC_WAIT(n)  asm volatile("cp.async.wait_group %0;" :: "n"(n) : "memory")

// mma.sync m16n8k8 tf32 (legacy tensor path, valid on compute_103)
__device__ __forceinline__ void mma_tf32(float* c,
                                         float a0, float a1, float a2, float a3,
                                         float b0, float b1) {
    asm volatile(
        "mma.sync.aligned.m16n8k8.row.col.f32.tf32.tf32.f32 "
        "{%0,%1,%2,%3}, {%4,%5,%6,%7}, {%8,%9}, {%0,%1,%2,%3};"
        : "+f"(c[0]), "+f"(c[1]), "+f"(c[2]), "+f"(c[3])
        : "r"(__float_as_uint(a0)), "r"(__float_as_uint(a1)),
          "r"(__float_as_uint(a2)), "r"(__float_as_uint(a3)),
          "r"(__float_as_uint(b0)), "r"(__float_as_uint(b1)));
}

// ---------------------------------------------------------------------------
// Kernel: zero the scores accumulator
// ---------------------------------------------------------------------------
__global__ __launch_bounds__(512) void zero_scores_kernel() {
    int i = blockIdx.x * 512 + threadIdx.x;
    g_scores[i] = 0.0f;
}

// ---------------------------------------------------------------------------
// Kernel: transpose W_mem [k][d] -> g_Wt [d][k]
// ---------------------------------------------------------------------------
__global__ __launch_bounds__(256) void transpose_kernel(const float* __restrict__ W) {
    __shared__ float t[32][33];
    int dblk = blockIdx.x * 32;
    int kblk = blockIdx.y * 32;
    int tx = threadIdx.x & 31;
    int ty = threadIdx.x >> 5;     // 0..7
    #pragma unroll
    for (int j = 0; j < 32; j += 8)
        t[ty + j][tx] = W[(size_t)(kblk + ty + j) * D_ + dblk + tx];
    __syncthreads();
    #pragma unroll
    for (int j = 0; j < 32; j += 8)
        g_Wt[(size_t)(dblk + ty + j) * M_ + kblk + tx] = t[tx][ty + j];
}

// ---------------------------------------------------------------------------
// Kernel: dec_feat[b][d] = decoder_state[b] @ W_dec
// ---------------------------------------------------------------------------
__global__ __launch_bounds__(256) void dec_feat_kernel(
    const float* __restrict__ decoder_state,
    const float* __restrict__ W_dec)
{
    __shared__ float ds[4][M_];
    int tid = threadIdx.x;
    int d   = blockIdx.x * 256 + tid;
    int bg  = blockIdx.y * 4;

    for (int i = tid; i < 4 * M_; i += 256)
        ds[i >> 10][i & (M_ - 1)] = decoder_state[(bg + (i >> 10)) * M_ + (i & (M_ - 1))];
    __syncthreads();

    float a0 = 0.f, a1 = 0.f, a2 = 0.f, a3 = 0.f;
    for (int m = 0; m < M_; m++) {
        float w = W_dec[(size_t)m * D_ + d];
        a0 += ds[0][m] * w; a1 += ds[1][m] * w;
        a2 += ds[2][m] * w; a3 += ds[3][m] * w;
    }
    g_decf[(bg + 0) * D_ + d] = a0;
    g_decf[(bg + 1) * D_ + d] = a1;
    g_decf[(bg + 2) * D_ + d] = a2;
    g_decf[(bg + 3) * D_ + d] = a3;
}

// ---------------------------------------------------------------------------
// Scores GEMM: C[s][d] = sum_k mem[b][s][k] * W_mem[k][d], fused
//   score[s] += sum_d Wv[d] * tanh(C[s][d] + decf[b][d])
//
// mma.sync m16n8k8 tf32, CTA tile 128x128x32, 8 warps (4x2), warp tile 32x64.
// 3-stage cp.async pipeline.  smem rows: 32 data floats + 4 pad (stride 36)
// -> all fragment LDS patterns are bank-conflict-free.
// A smem is [s][k] (row-major), B smem is [d][k] (n-major, from g_Wt).
// ---------------------------------------------------------------------------
#define SROW 36
#define STAGE_FLOATS (2 * 128 * SROW)          // A tile + B tile = 9216 floats
#define STAGES 3
#define SM_BYTES (STAGES * STAGE_FLOATS * 4)   // 110592

extern __shared__ float smem[];

__global__ __launch_bounds__(256, 2)
void scores_mma_kernel(const float* __restrict__ memory_bank,
                       const float* __restrict__ W_v)
{
    int tid  = threadIdx.x;
    int wid  = tid >> 5;
    int lane = tid & 31;
    int grp  = lane >> 2;         // 0..7
    int q    = lane & 3;          // 0..3
    int warp_m = wid & 3;         // 4 warps along s
    int warp_n = wid >> 2;        // 2 warps along d

    int d_base = blockIdx.x * 128;     // d fastest-varying -> A reuse in L2
    int s_base = blockIdx.y * 128;
    int b      = blockIdx.z;

    const float* Abase = memory_bank + ((size_t)b * S_ + s_base) * M_;
    const float* Bbase = g_Wt + (size_t)d_base * M_;

    uint32_t smem_base = smem_u32(smem);

    // per-thread global-load coords (4 A chunks + 4 B chunks of 16B per stage)
    int lrow = tid >> 3;          // 0..31 (combined with +32*i)
    int lc   = tid & 7;           // 16B chunk within row

    auto load_stage = [&](int kt, int st) {
        int k0 = kt * 32;
        uint32_t dstA = smem_base + (uint32_t)(st * STAGE_FLOATS) * 4;
        uint32_t dstB = dstA + 128 * SROW * 4;
        #pragma unroll
        for (int i = 0; i < 4; i++) {
            int row = lrow + i * 32;
            cp_async16(dstA + (uint32_t)(row * SROW + lc * 4) * 4,
                       Abase + (size_t)row * M_ + k0 + lc * 4);
        }
        #pragma unroll
        for (int i = 0; i < 4; i++) {
            int row = lrow + i * 32;
            cp_async16(dstB + (uint32_t)(row * SROW + lc * 4) * 4,
                       Bbase + (size_t)row * M_ + k0 + lc * 4);
        }
        CP_ASYNC_COMMIT();
    };

    float acc[2][8][4];
    #pragma unroll
    for (int mt = 0; mt < 2; mt++)
        #pragma unroll
        for (int nt = 0; nt < 8; nt++)
            #pragma unroll
            for (int i = 0; i < 4; i++)
                acc[mt][nt][i] = 0.0f;

    // prologue: 2 stages in flight
    load_stage(0, 0);
    load_stage(1, 1);

    for (int kt = 0; kt < 32; kt++) {
        if (kt == 31) { CP_ASYNC_WAIT(0); } else { CP_ASYNC_WAIT(1); }
        __syncthreads();

        if (kt + 2 < 32) load_stage(kt + 2, (kt + 2) % 3);

        const float* stA = smem + (kt % 3) * STAGE_FLOATS;
        const float* stB = stA + 128 * SROW;
        // conflict-free fragment base pointers
        const float* pA = stA + (warp_m * 32 + grp) * SROW + q;
        const float* pB = stB + (warp_n * 64 + grp) * SROW + q;

        #pragma unroll
        for (int ks = 0; ks < 4; ks++) {
            float b0[8], b1[8];
            #pragma unroll
            for (int nt = 0; nt < 8; nt++) {
                b0[nt] = pB[nt * 8 * SROW + ks * 8];
                b1[nt] = pB[nt * 8 * SROW + ks * 8 + 4];
            }
            #pragma unroll
            for (int mt = 0; mt < 2; mt++) {
                float a0 = pA[mt * 16 * SROW + ks * 8];
                float a1 = pA[(mt * 16 + 8) * SROW + ks * 8];
                float a2 = pA[mt * 16 * SROW + ks * 8 + 4];
                float a3 = pA[(mt * 16 + 8) * SROW + ks * 8 + 4];
                #pragma unroll
                for (int nt = 0; nt < 8; nt++)
                    mma_tf32(acc[mt][nt], a0, a1, a2, a3, b0[nt], b1[nt]);
            }
        }
    }

    // ---- epilogue: score[s] += sum_d Wv[d]*tanh(C + decf[d]) ----
    __syncthreads();
    float* s_df = smem;           // [128]
    float* s_wv = smem + 128;     // [128]
    if (tid < 128)       s_df[tid] = g_decf[b * D_ + d_base + tid];
    else                 s_wv[tid - 128] = W_v[d_base + tid - 128];
    __syncthreads();

    float part[4] = {0.f, 0.f, 0.f, 0.f};
    #pragma unroll
    for (int mt = 0; mt < 2; mt++) {
        #pragma unroll
        for (int nt = 0; nt < 8; nt++) {
            int col0 = warp_n * 64 + nt * 8 + 2 * q;
            float wv0 = s_wv[col0], wv1 = s_wv[col0 + 1];
            float df0 = s_df[col0], df1 = s_df[col0 + 1];
            part[2 * mt]     += wv0 * tanhf(acc[mt][nt][0] + df0)
                              + wv1 * tanhf(acc[mt][nt][1] + df1);
            part[2 * mt + 1] += wv0 * tanhf(acc[mt][nt][2] + df0)
                              + wv1 * tanhf(acc[mt][nt][3] + df1);
        }
    }
    #pragma unroll
    for (int i = 0; i < 4; i++) {
        part[i] += __shfl_xor_sync(0xFFFFFFFFu, part[i], 1);
        part[i] += __shfl_xor_sync(0xFFFFFFFFu, part[i], 2);
    }
    if (q == 0) {
        int rbase = b * S_ + s_base + warp_m * 32 + grp;
        atomicAdd(&g_scores[rbase],      part[0]);   // row grp       (mt0)
        atomicAdd(&g_scores[rbase + 8],  part[1]);   // row grp+8     (mt0)
        atomicAdd(&g_scores[rbase + 16], part[2]);   // row grp+16    (mt1)
        atomicAdd(&g_scores[rbase + 24], part[3]);   // row grp+24    (mt1)
    }
}

// ---------------------------------------------------------------------------
// Softmax over S per batch (masked)
// ---------------------------------------------------------------------------
__global__ __launch_bounds__(256) void softmax_kernel(
    const int* __restrict__ src_mask,
    float* __restrict__ attn_out)
{
    __shared__ float red[8];
    int b = blockIdx.x, tid = threadIdx.x;
    int lane = tid & 31, wid = tid >> 5;

    float v[8];
    float mx = -3.4e38f;
    #pragma unroll
    for (int j = 0; j < 8; j++) {
        int idx = tid + j * 256;
        float s = g_scores[b * S_ + idx];
        if (src_mask[b * S_ + idx] == 0) s = -3.4e38f;
        v[j] = s;
        mx = fmaxf(mx, s);
    }
    #pragma unroll
    for (int off = 16; off > 0; off >>= 1)
        mx = fmaxf(mx, __shfl_xor_sync(0xFFFFFFFFu, mx, off));
    if (lane == 0) red[wid] = mx;
    __syncthreads();
    if (tid == 0) {
        float m2 = red[0];
        #pragma unroll
        for (int w = 1; w < 8; w++) m2 = fmaxf(m2, red[w]);
        red[0] = m2;
    }
    __syncthreads();
    mx = red[0];
    __syncthreads();

    float e[8];
    float sum = 0.0f;
    #pragma unroll
    for (int j = 0; j < 8; j++) {
        e[j] = __expf(v[j] - mx);
        sum += e[j];
    }
    #pragma unroll
    for (int off = 16; off > 0; off >>= 1)
        sum += __shfl_xor_sync(0xFFFFFFFFu, sum, off);
    if (lane == 0) red[wid] = sum;
    __syncthreads();
    if (tid == 0) {
        float s2 = 0.0f;
        #pragma unroll
        for (int w = 0; w < 8; w++) s2 += red[w];
        red[0] = s2;
    }
    __syncthreads();
    float inv = 1.0f / red[0];

    #pragma unroll
    for (int j = 0; j < 8; j++)
        attn_out[b * S_ + tid + j * 256] = e[j] * inv;
}

// ---------------------------------------------------------------------------
// context[b][m] = sum_s attn[b][s] * mem[b][s][m]
// ---------------------------------------------------------------------------
__global__ __launch_bounds__(256) void context_kernel(
    const float* __restrict__ attn,
    const float* __restrict__ memory_bank,
    float* __restrict__ ctx_out)
{
    __shared__ float sa[S_];
    int tid = threadIdx.x;
    int b   = blockIdx.y;
    int m0  = blockIdx.x * 256;

    #pragma unroll
    for (int j = 0; j < 8; j++)
        sa[tid + j * 256] = attn[b * S_ + tid + j * 256];
    __syncthreads();

    const float* base = memory_bank + (size_t)b * S_ * M_ + m0 + tid;
    float a0 = 0.f, a1 = 0.f, a2 = 0.f, a3 = 0.f;
    for (int s = 0; s < S_; s += 4) {
        a0 += sa[s + 0] * base[(size_t)(s + 0) * M_];
        a1 += sa[s + 1] * base[(size_t)(s + 1) * M_];
        a2 += sa[s + 2] * base[(size_t)(s + 2) * M_];
        a3 += sa[s + 3] * base[(size_t)(s + 3) * M_];
    }
    ctx_out[b * M_ + m0 + tid] = (a0 + a1) + (a2 + a3);
}

// ---------------------------------------------------------------------------
// Launch
// ---------------------------------------------------------------------------
extern "C" void kernel_launch(void* const* d_in, const int* in_sizes, int n_in,
                              void* d_out, int out_size)
{
    const float* decoder_state = (const float*)d_in[0];
    const float* memory_bank   = (const float*)d_in[1];
    const int*   src_mask      = (const int*)  d_in[2];
    const float* W_v           = (const float*)d_in[3];
    const float* W_dec         = (const float*)d_in[4];
    const float* W_mem         = (const float*)d_in[5];

    float* out  = (float*)d_out;
    float* ctx  = out;                 // [64, 1024]
    float* attn = out + B_ * M_;       // [64, 2048]

    cudaFuncSetAttribute(scores_mma_kernel,
                         cudaFuncAttributeMaxDynamicSharedMemorySize, SM_BYTES);

    zero_scores_kernel<<<B_ * S_ / 512, 512>>>();
    transpose_kernel<<<dim3(32, 32), 256>>>(W_mem);
    dec_feat_kernel<<<dim3(D_ / 256, B_ / 4), 256>>>(decoder_state, W_dec);
    scores_mma_kernel<<<dim3(D_ / 128, S_ / 128, B_), 256, SM_BYTES>>>(memory_bank, W_v);
    softmax_kernel<<<B_, 256>>>(src_mask, attn);
    context_kernel<<<dim3(M_ / 256, B_), 256>>>(attn, memory_bank, ctx);
}

// round 5
// speedup vs baseline: 2.9973x; 1.1420x over previous
#include <cuda_runtime.h>
#include <cuda_bf16.h>
#include <cstdint>
#include <math.h>

// Problem sizes (fixed)
#define B_   64
#define S_   2048
#define M_   1024   // K of scores GEMM (memory feature dim)
#define D_   1024   // N of scores GEMM (decoder feature dim)

// ---------------------------------------------------------------------------
// Scratch (no allocations allowed)
// ---------------------------------------------------------------------------
__device__ float g_scores[B_ * S_];          // 512 KB
__device__ float g_decf[B_ * D_];            // 256 KB
__device__ float g_Wt[D_ * M_];              // 4 MB: W_mem transposed [d][k], K pair-permuted

// ---------------------------------------------------------------------------
// Helpers
// ---------------------------------------------------------------------------
__device__ __forceinline__ uint32_t smem_u32(const void* p) {
    uint32_t a;
    asm("{ .reg .u64 t; cvta.to.shared.u64 t, %1; cvt.u32.u64 %0, t; }"
        : "=r"(a) : "l"(p));
    return a;
}

__device__ __forceinline__ void cp_async16(uint32_t dst, const void* src) {
    asm volatile("cp.async.cg.shared.global [%0], [%1], 16;"
                 :: "r"(dst), "l"(src));
}
#define CP_ASYNC_COMMIT() asm volatile("cp.async.commit_group;" ::: "memory")
#define CP_ASYNC_WAIT(n)  asm volatile("cp.async.wait_group %0;" :: "n"(n) : "memory")

// mma.sync m16n8k8 tf32 (legacy tensor path, valid on compute_103)
__device__ __forceinline__ void mma_tf32(float* c,
                                         float a0, float a1, float a2, float a3,
                                         float b0, float b1) {
    asm volatile(
        "mma.sync.aligned.m16n8k8.row.col.f32.tf32.tf32.f32 "
        "{%0,%1,%2,%3}, {%4,%5,%6,%7}, {%8,%9}, {%0,%1,%2,%3};"
        : "+f"(c[0]), "+f"(c[1]), "+f"(c[2]), "+f"(c[3])
        : "r"(__float_as_uint(a0)), "r"(__float_as_uint(a1)),
          "r"(__float_as_uint(a2)), "r"(__float_as_uint(a3)),
          "r"(__float_as_uint(b0)), "r"(__float_as_uint(b1)));
}

// ---------------------------------------------------------------------------
// Kernel: zero the scores accumulator
// ---------------------------------------------------------------------------
__global__ __launch_bounds__(512) void zero_scores_kernel() {
    int i = blockIdx.x * 512 + threadIdx.x;
    g_scores[i] = 0.0f;
}

// ---------------------------------------------------------------------------
// Kernel: transpose W_mem [k][d] -> g_Wt [d][k'], with K pair-permutation
// within each 8-block so that (q, q+4) land at (2q, 2q+1):
//   p(k) = (k & ~7) | ((k&3)<<1) | ((k>>2)&1)
// ---------------------------------------------------------------------------
__global__ __launch_bounds__(256) void transpose_kernel(const float* __restrict__ W) {
    __shared__ float t[32][33];
    int dblk = blockIdx.x * 32;
    int kblk = blockIdx.y * 32;
    int tx = threadIdx.x & 31;
    int ty = threadIdx.x >> 5;     // 0..7
    #pragma unroll
    for (int j = 0; j < 32; j += 8)
        t[ty + j][tx] = W[(size_t)(kblk + ty + j) * D_ + dblk + tx];
    __syncthreads();
    int kp = (tx & ~7) | ((tx & 3) << 1) | ((tx >> 2) & 1);   // pair permutation
    #pragma unroll
    for (int j = 0; j < 32; j += 8)
        g_Wt[(size_t)(dblk + ty + j) * M_ + kblk + kp] = t[tx][ty + j];
}

// ---------------------------------------------------------------------------
// Kernel: dec_feat[b][d] = decoder_state[b] @ W_dec
// ---------------------------------------------------------------------------
__global__ __launch_bounds__(256) void dec_feat_kernel(
    const float* __restrict__ decoder_state,
    const float* __restrict__ W_dec)
{
    __shared__ float ds[4][M_];
    int tid = threadIdx.x;
    int d   = blockIdx.x * 256 + tid;
    int bg  = blockIdx.y * 4;

    for (int i = tid; i < 4 * M_; i += 256)
        ds[i >> 10][i & (M_ - 1)] = decoder_state[(bg + (i >> 10)) * M_ + (i & (M_ - 1))];
    __syncthreads();

    float a0 = 0.f, a1 = 0.f, a2 = 0.f, a3 = 0.f;
    for (int m = 0; m < M_; m++) {
        float w = W_dec[(size_t)m * D_ + d];
        a0 += ds[0][m] * w; a1 += ds[1][m] * w;
        a2 += ds[2][m] * w; a3 += ds[3][m] * w;
    }
    g_decf[(bg + 0) * D_ + d] = a0;
    g_decf[(bg + 1) * D_ + d] = a1;
    g_decf[(bg + 2) * D_ + d] = a2;
    g_decf[(bg + 3) * D_ + d] = a3;
}

// ---------------------------------------------------------------------------
// Scores GEMM: C[s][d] = sum_k mem[b][s][k] * W_mem[k][d], fused
//   score[s] += sum_d Wv[d] * tanh(C[s][d] + decf[b][d])
//
// mma.sync m16n8k8 tf32, CTA tile 128x128x32, 8 warps (4x2), warp tile 32x64.
// 3-stage cp.async pipeline.
// A smem: [s][k] stride 32, XOR chunk swizzle (c ^= row&7) -> scalar LDS
//         conflict-free.
// B smem: [d][k'] stride 40 (pair-permuted K) -> LDS.64 fragments,
//         conflict-free (stride 40 = 8 mod 32 banks).
// ---------------------------------------------------------------------------
#define A_FLOATS (128 * 32)
#define B_STRIDE 40
#define STAGE_FLOATS (A_FLOATS + 128 * B_STRIDE)    // 9216 floats (36864 B)
#define STAGES 3
#define SM_BYTES (STAGES * STAGE_FLOATS * 4)        // 110592

extern __shared__ float smem[];

__global__ __launch_bounds__(256, 2)
void scores_mma_kernel(const float* __restrict__ memory_bank,
                       const float* __restrict__ W_v)
{
    int tid  = threadIdx.x;
    int wid  = tid >> 5;
    int lane = tid & 31;
    int grp  = lane >> 2;         // 0..7
    int q    = lane & 3;          // 0..3
    int warp_m = wid & 3;         // 4 warps along s
    int warp_n = wid >> 2;        // 2 warps along d

    int d_base = blockIdx.x * 128;     // d fastest-varying -> A reuse in L2
    int s_base = blockIdx.y * 128;
    int b      = blockIdx.z;

    const float* Abase = memory_bank + ((size_t)b * S_ + s_base) * M_;
    const float* Bbase = g_Wt + (size_t)d_base * M_;

    uint32_t smem_base = smem_u32(smem);

    // per-thread global-load coords (4 A chunks + 4 B chunks of 16B per stage)
    int lrow = tid >> 3;          // 0..31 (combined with +32*i)
    int lc   = tid & 7;           // 16B chunk within row
    int lcA  = lc ^ (lrow & 7);   // XOR-swizzled A chunk (row&7 == lrow&7)

    auto load_stage = [&](int kt, int st) {
        int k0 = kt * 32;
        uint32_t dstA = smem_base + (uint32_t)(st * STAGE_FLOATS) * 4;
        uint32_t dstB = dstA + A_FLOATS * 4;
        #pragma unroll
        for (int i = 0; i < 4; i++) {
            int row = lrow + i * 32;
            cp_async16(dstA + (uint32_t)(row * 32 + lcA * 4) * 4,
                       Abase + (size_t)row * M_ + k0 + lc * 4);
        }
        #pragma unroll
        for (int i = 0; i < 4; i++) {
            int row = lrow + i * 32;
            cp_async16(dstB + (uint32_t)(row * B_STRIDE + lc * 4) * 4,
                       Bbase + (size_t)row * M_ + k0 + lc * 4);
        }
        CP_ASYNC_COMMIT();
    };

    float acc[2][8][4];
    #pragma unroll
    for (int mt = 0; mt < 2; mt++)
        #pragma unroll
        for (int nt = 0; nt < 8; nt++)
            #pragma unroll
            for (int i = 0; i < 4; i++)
                acc[mt][nt][i] = 0.0f;

    // prologue: 2 stages in flight
    load_stage(0, 0);
    load_stage(1, 1);

    int rowA0 = warp_m * 32 + grp;       // A fragment base row (mt adds 16, +8)
    int rowB0 = warp_n * 64 + grp;       // B fragment base row (nt adds 8)

    for (int kt = 0; kt < 32; kt++) {
        if (kt == 31) { CP_ASYNC_WAIT(0); } else { CP_ASYNC_WAIT(1); }
        __syncthreads();

        if (kt + 2 < 32) load_stage(kt + 2, (kt + 2) % 3);

        const float* stA = smem + (kt % 3) * STAGE_FLOATS;
        const float* stB = stA + A_FLOATS;
        const float* bb  = stB + (size_t)rowB0 * B_STRIDE + 2 * q;

        #pragma unroll
        for (int ks = 0; ks < 4; ks++) {
            // B fragments: one LDS.64 each (pair-permuted K)
            float2 bf[8];
            #pragma unroll
            for (int nt = 0; nt < 8; nt++)
                bf[nt] = *reinterpret_cast<const float2*>(
                    bb + nt * 8 * B_STRIDE + ks * 8);

            int c0 = ((2 * ks) ^ grp) * 4 + q;       // k = ks*8+q   (swizzled)
            int c1 = ((2 * ks + 1) ^ grp) * 4 + q;   // k = ks*8+q+4 (swizzled)
            #pragma unroll
            for (int mt = 0; mt < 2; mt++) {
                int r0 = rowA0 + mt * 16;
                float a0 = stA[r0 * 32 + c0];
                float a1 = stA[(r0 + 8) * 32 + c0];
                float a2 = stA[r0 * 32 + c1];
                float a3 = stA[(r0 + 8) * 32 + c1];
                #pragma unroll
                for (int nt = 0; nt < 8; nt++)
                    mma_tf32(acc[mt][nt], a0, a1, a2, a3, bf[nt].x, bf[nt].y);
            }
        }
    }

    // ---- epilogue: score[s] += sum_d Wv[d]*tanh(C + decf[d]) ----
    __syncthreads();
    float* s_df = smem;           // [128]
    float* s_wv = smem + 128;     // [128]
    if (tid < 128)       s_df[tid] = g_decf[b * D_ + d_base + tid];
    else                 s_wv[tid - 128] = W_v[d_base + tid - 128];
    __syncthreads();

    float part[4] = {0.f, 0.f, 0.f, 0.f};
    #pragma unroll
    for (int mt = 0; mt < 2; mt++) {
        #pragma unroll
        for (int nt = 0; nt < 8; nt++) {
            int col0 = warp_n * 64 + nt * 8 + 2 * q;
            float wv0 = s_wv[col0], wv1 = s_wv[col0 + 1];
            float df0 = s_df[col0], df1 = s_df[col0 + 1];
            part[2 * mt]     += wv0 * tanhf(acc[mt][nt][0] + df0)
                              + wv1 * tanhf(acc[mt][nt][1] + df1);
            part[2 * mt + 1] += wv0 * tanhf(acc[mt][nt][2] + df0)
                              + wv1 * tanhf(acc[mt][nt][3] + df1);
        }
    }
    #pragma unroll
    for (int i = 0; i < 4; i++) {
        part[i] += __shfl_xor_sync(0xFFFFFFFFu, part[i], 1);
        part[i] += __shfl_xor_sync(0xFFFFFFFFu, part[i], 2);
    }
    if (q == 0) {
        int rbase = b * S_ + s_base + warp_m * 32 + grp;
        atomicAdd(&g_scores[rbase],      part[0]);
        atomicAdd(&g_scores[rbase + 8],  part[1]);
        atomicAdd(&g_scores[rbase + 16], part[2]);
        atomicAdd(&g_scores[rbase + 24], part[3]);
    }
}

// ---------------------------------------------------------------------------
// Softmax over S per batch (masked)
// ---------------------------------------------------------------------------
__global__ __launch_bounds__(256) void softmax_kernel(
    const int* __restrict__ src_mask,
    float* __restrict__ attn_out)
{
    __shared__ float red[8];
    int b = blockIdx.x, tid = threadIdx.x;
    int lane = tid & 31, wid = tid >> 5;

    float v[8];
    float mx = -3.4e38f;
    #pragma unroll
    for (int j = 0; j < 8; j++) {
        int idx = tid + j * 256;
        float s = g_scores[b * S_ + idx];
        if (src_mask[b * S_ + idx] == 0) s = -3.4e38f;
        v[j] = s;
        mx = fmaxf(mx, s);
    }
    #pragma unroll
    for (int off = 16; off > 0; off >>= 1)
        mx = fmaxf(mx, __shfl_xor_sync(0xFFFFFFFFu, mx, off));
    if (lane == 0) red[wid] = mx;
    __syncthreads();
    if (tid == 0) {
        float m2 = red[0];
        #pragma unroll
        for (int w = 1; w < 8; w++) m2 = fmaxf(m2, red[w]);
        red[0] = m2;
    }
    __syncthreads();
    mx = red[0];
    __syncthreads();

    float e[8];
    float sum = 0.0f;
    #pragma unroll
    for (int j = 0; j < 8; j++) {
        e[j] = __expf(v[j] - mx);
        sum += e[j];
    }
    #pragma unroll
    for (int off = 16; off > 0; off >>= 1)
        sum += __shfl_xor_sync(0xFFFFFFFFu, sum, off);
    if (lane == 0) red[wid] = sum;
    __syncthreads();
    if (tid == 0) {
        float s2 = 0.0f;
        #pragma unroll
        for (int w = 0; w < 8; w++) s2 += red[w];
        red[0] = s2;
    }
    __syncthreads();
    float inv = 1.0f / red[0];

    #pragma unroll
    for (int j = 0; j < 8; j++)
        attn_out[b * S_ + tid + j * 256] = e[j] * inv;
}

// ---------------------------------------------------------------------------
// context[b][m] = sum_s attn[b][s] * mem[b][s][m]
// ---------------------------------------------------------------------------
__global__ __launch_bounds__(256) void context_kernel(
    const float* __restrict__ attn,
    const float* __restrict__ memory_bank,
    float* __restrict__ ctx_out)
{
    __shared__ float sa[S_];
    int tid = threadIdx.x;
    int b   = blockIdx.y;
    int m0  = blockIdx.x * 256;

    #pragma unroll
    for (int j = 0; j < 8; j++)
        sa[tid + j * 256] = attn[b * S_ + tid + j * 256];
    __syncthreads();

    const float* base = memory_bank + (size_t)b * S_ * M_ + m0 + tid;
    float a0 = 0.f, a1 = 0.f, a2 = 0.f, a3 = 0.f;
    for (int s = 0; s < S_; s += 4) {
        a0 += sa[s + 0] * base[(size_t)(s + 0) * M_];
        a1 += sa[s + 1] * base[(size_t)(s + 1) * M_];
        a2 += sa[s + 2] * base[(size_t)(s + 2) * M_];
        a3 += sa[s + 3] * base[(size_t)(s + 3) * M_];
    }
    ctx_out[b * M_ + m0 + tid] = (a0 + a1) + (a2 + a3);
}

// ---------------------------------------------------------------------------
// Launch
// ---------------------------------------------------------------------------
extern "C" void kernel_launch(void* const* d_in, const int* in_sizes, int n_in,
                              void* d_out, int out_size)
{
    const float* decoder_state = (const float*)d_in[0];
    const float* memory_bank   = (const float*)d_in[1];
    const int*   src_mask      = (const int*)  d_in[2];
    const float* W_v           = (const float*)d_in[3];
    const float* W_dec         = (const float*)d_in[4];
    const float* W_mem         = (const float*)d_in[5];

    float* out  = (float*)d_out;
    float* ctx  = out;                 // [64, 1024]
    float* attn = out + B_ * M_;       // [64, 2048]

    cudaFuncSetAttribute(scores_mma_kernel,
                         cudaFuncAttributeMaxDynamicSharedMemorySize, SM_BYTES);

    zero_scores_kernel<<<B_ * S_ / 512, 512>>>();
    transpose_kernel<<<dim3(32, 32), 256>>>(W_mem);
    dec_feat_kernel<<<dim3(D_ / 256, B_ / 4), 256>>>(decoder_state, W_dec);
    scores_mma_kernel<<<dim3(D_ / 128, S_ / 128, B_), 256, SM_BYTES>>>(memory_bank, W_v);
    softmax_kernel<<<B_, 256>>>(src_mask, attn);
    context_kernel<<<dim3(M_ / 256, B_), 256>>>(attn, memory_bank, ctx);
}